// round 4
// baseline (speedup 1.0000x reference)
#include <cuda_runtime.h>
#include <math.h>

// Problem constants
#define T_  1024
#define D_  768
#define H_  12
#define HD_ 64
#define FF_ 3072
#define V_  8192
#define EPS 1e-5f

// ---------------- scratch (device globals; allocation-free) ----------------
__device__ float g_xnorm [T_ * D_];                 // ln1 output
__device__ float g_qk    [T_ * 2 * D_];             // qk projection [T, 1536]
__device__ float g_v     [H_ * T_ * HD_];           // v per head [H,T,64]
__device__ float g_y     [T_ * H_ * HD_];           // attn out [T,H,64]
__device__ float g_x2    [T_ * D_];                 // ln2 output
__device__ float g_h     [(long long)H_ * T_ * FF_];// gelu(fc) [H,T,FF]  (~151MB)
__device__ float g_h2    [H_ * T_ * HD_];           // proj out [H,T,64]
__device__ float g_xhat  [H_ * T_ * HD_];           // dict LN out
__device__ float g_xrec  [H_ * T_ * HD_];           // reconstruction
__device__ float g_lpart [H_ * T_];                 // per-(h,t) loss partials

// ALiBi slopes for H=12 (closest power 8 + extras), computed in double, hardcoded
__constant__ float c_slopes[H_] = {
    0.5f, 0.25f, 0.125f, 0.0625f, 0.03125f, 0.015625f, 0.0078125f, 0.00390625f,
    0.70710678118654752f, 0.5f, 0.35355339059327376f, 0.25f
};

// ---------------- reduction helpers ----------------
__device__ __forceinline__ float block_reduce_sum(float v) {
    __shared__ float sm[33];
    int lane = threadIdx.x & 31, wid = threadIdx.x >> 5;
    #pragma unroll
    for (int o = 16; o; o >>= 1) v += __shfl_xor_sync(0xffffffffu, v, o);
    __syncthreads();
    if (lane == 0) sm[wid] = v;
    __syncthreads();
    int nw = (blockDim.x + 31) >> 5;
    if (wid == 0) {
        v = (lane < nw) ? sm[lane] : 0.f;
        #pragma unroll
        for (int o = 16; o; o >>= 1) v += __shfl_xor_sync(0xffffffffu, v, o);
        if (lane == 0) sm[32] = v;
    }
    __syncthreads();
    return sm[32];
}

__device__ __forceinline__ float block_reduce_max(float v) {
    __shared__ float sm[33];
    int lane = threadIdx.x & 31, wid = threadIdx.x >> 5;
    #pragma unroll
    for (int o = 16; o; o >>= 1) v = fmaxf(v, __shfl_xor_sync(0xffffffffu, v, o));
    __syncthreads();
    if (lane == 0) sm[wid] = v;
    __syncthreads();
    int nw = (blockDim.x + 31) >> 5;
    if (wid == 0) {
        v = (lane < nw) ? sm[lane] : -INFINITY;
        #pragma unroll
        for (int o = 16; o; o >>= 1) v = fmaxf(v, __shfl_xor_sync(0xffffffffu, v, o));
        if (lane == 0) sm[32] = v;
    }
    __syncthreads();
    return sm[32];
}

// ---------------- add + layernorm over D=768 ----------------
__global__ void add_ln_kernel(const float* __restrict__ a, const float* __restrict__ b,
                              const float* __restrict__ w, const float* __restrict__ bs,
                              float* __restrict__ out) {
    int t = blockIdx.x;
    long base = (long)t * D_;
    float x[3];
    float s = 0.f;
    #pragma unroll
    for (int i = 0; i < 3; i++) {
        int c = threadIdx.x + 256 * i;
        x[i] = a[base + c] + b[base + c];
        s += x[i];
    }
    s = block_reduce_sum(s);
    float mu = s * (1.f / D_);
    float q = 0.f;
    #pragma unroll
    for (int i = 0; i < 3; i++) { float d = x[i] - mu; q += d * d; }
    q = block_reduce_sum(q);
    float rstd = rsqrtf(q * (1.f / D_) + EPS);
    #pragma unroll
    for (int i = 0; i < 3; i++) {
        int c = threadIdx.x + 256 * i;
        out[base + c] = (x[i] - mu) * rstd * w[c] + bs[c];
    }
}

// ---------------- generic batched tiled GEMM: C = A * op(B) + bias ----------
// A: [M,K] row-major (lda). TRANS_B: B is [N,K] (ldb over K); else B is [K,N].
// 64x64x16 tiles, 256 threads, 4x4 per thread. All dims assumed divisible.
template<bool TRANS_B, bool GELU>
__global__ void gemm_bias(const float* __restrict__ A, const float* __restrict__ B,
                          const float* __restrict__ bias, float* __restrict__ C,
                          int M, int N, int K,
                          long long sA, long long sB, long long sBias, long long sC,
                          int lda, int ldb, int ldc) {
    int bz = blockIdx.z;
    A += bz * sA; B += bz * sB; C += bz * sC;
    if (bias) bias += bz * sBias;

    __shared__ float As[16][64];
    __shared__ float Bs[16][64];

    int tid = threadIdx.x;
    int row0 = blockIdx.y * 64;
    int col0 = blockIdx.x * 64;
    int tr = (tid >> 4) * 4;
    int tc = (tid & 15) * 4;

    float acc[4][4] = {};

    for (int k0 = 0; k0 < K; k0 += 16) {
        { // A tile (transposed store)
            int r  = tid >> 2;
            int kk = (tid & 3) * 4;
            float4 v = *(const float4*)(A + (long)(row0 + r) * lda + k0 + kk);
            As[kk + 0][r] = v.x; As[kk + 1][r] = v.y;
            As[kk + 2][r] = v.z; As[kk + 3][r] = v.w;
        }
        if (TRANS_B) {
            int n  = tid >> 2;
            int kk = (tid & 3) * 4;
            float4 v = *(const float4*)(B + (long)(col0 + n) * ldb + k0 + kk);
            Bs[kk + 0][n] = v.x; Bs[kk + 1][n] = v.y;
            Bs[kk + 2][n] = v.z; Bs[kk + 3][n] = v.w;
        } else {
            int kk = tid >> 4;
            int n  = (tid & 15) * 4;
            float4 v = *(const float4*)(B + (long)(k0 + kk) * ldb + col0 + n);
            Bs[kk][n] = v.x; Bs[kk][n + 1] = v.y; Bs[kk][n + 2] = v.z; Bs[kk][n + 3] = v.w;
        }
        __syncthreads();
        #pragma unroll
        for (int kk = 0; kk < 16; kk++) {
            float a[4], b[4];
            #pragma unroll
            for (int i = 0; i < 4; i++) a[i] = As[kk][tr + i];
            #pragma unroll
            for (int j = 0; j < 4; j++) b[j] = Bs[kk][tc + j];
            #pragma unroll
            for (int i = 0; i < 4; i++)
                #pragma unroll
                for (int j = 0; j < 4; j++)
                    acc[i][j] += a[i] * b[j];
        }
        __syncthreads();
    }
    #pragma unroll
    for (int i = 0; i < 4; i++) {
        long r = row0 + tr + i;
        #pragma unroll
        for (int j = 0; j < 4; j++) {
            int c = col0 + tc + j;
            float v = acc[i][j];
            if (bias) v += bias[c];
            if (GELU) v = 0.5f * v * (1.0f + erff(v * 0.70710678118654752f));
            C[r * ldc + c] = v;
        }
    }
}

// ---------------- v = per-head mix of xt heads by v_fact --------------------
__global__ void v_mix_kernel(const float* __restrict__ xt, const float* __restrict__ vf,
                             float* __restrict__ v) {
    int t = blockIdx.x, h = blockIdx.y, d = threadIdx.x;
    float acc = 0.f;
    #pragma unroll
    for (int j = 0; j < H_; j++)
        acc += vf[h * H_ + j] * xt[(long)t * D_ + j * HD_ + d];
    v[((long)h * T_ + t) * HD_ + d] = acc;
}

// ---------------- attention: one block per (query i, head h) ----------------
__global__ void attn_kernel(const float* __restrict__ qk, const float* __restrict__ v,
                            float* __restrict__ y) {
    int i = blockIdx.x, h = blockIdx.y;
    __shared__ float qs[HD_];
    __shared__ float ss[T_];
    __shared__ float red[256];
    int tid = threadIdx.x;

    if (tid < HD_) qs[tid] = qk[(long)i * (2 * D_) + h * HD_ + tid];
    __syncthreads();

    float slope = c_slopes[h];
    float lmax = -INFINITY;
    for (int j = tid; j < T_; j += 256) {
        float s;
        if (j <= i) {
            const float* kp = qk + (long)j * (2 * D_) + D_ + h * HD_;
            float d = 0.f;
            #pragma unroll
            for (int e = 0; e < HD_; e++) d += qs[e] * kp[e];
            s = d * 0.125f + slope * (float)(j - i);
        } else s = -INFINITY;
        ss[j] = s;
        lmax = fmaxf(lmax, s);
    }
    float mx = block_reduce_max(lmax);

    float lsum = 0.f;
    for (int j = tid; j < T_; j += 256) {
        float e = (j <= i) ? __expf(ss[j] - mx) : 0.f;
        ss[j] = e;
        lsum += e;
    }
    float total = block_reduce_sum(lsum);

    // output: 4 chunks x 64 dims
    int d = tid & 63, c = tid >> 6;
    float acc = 0.f;
    for (int j = c; j <= i; j += 4)
        acc += ss[j] * v[((long)h * T_ + j) * HD_ + d];
    red[tid] = acc;
    __syncthreads();
    if (tid < HD_) {
        float o = (red[tid] + red[tid + 64] + red[tid + 128] + red[tid + 192]) / total;
        y[((long)i * H_ + h) * HD_ + tid] = o;
    }
}

// ---------------- output mix + residual: xt_new -----------------------------
__global__ void mix_out_kernel(const float* __restrict__ xt, const float* __restrict__ of,
                               const float* __restrict__ y, float* __restrict__ xt_new) {
    int idx = blockIdx.x * 256 + threadIdx.x;
    if (idx >= T_ * D_) return;
    int t = idx / D_;
    int c = idx - t * D_;
    int i = c >> 6, d = c & 63;
    float acc = xt[idx];
    #pragma unroll
    for (int j = 0; j < H_; j++)
        acc += of[i * H_ + j] * y[((long)t * H_ + j) * HD_ + d];
    xt_new[idx] = acc;
}

// ---------------- layernorm over HD=64 (dict LN) -----------------------------
__global__ void ln64_kernel(const float* __restrict__ in, const float* __restrict__ w,
                            const float* __restrict__ b, float* __restrict__ out) {
    int idx = blockIdx.x;          // h*T + t
    int h = idx >> 10;
    int l = threadIdx.x;           // 32 threads
    const float* p = in + (long)idx * HD_;
    float x0 = p[l], x1 = p[l + 32];
    float s = x0 + x1;
    #pragma unroll
    for (int o = 16; o; o >>= 1) s += __shfl_xor_sync(0xffffffffu, s, o);
    float mu = s * (1.f / HD_);
    float d0 = x0 - mu, d1 = x1 - mu;
    float q = d0 * d0 + d1 * d1;
    #pragma unroll
    for (int o = 16; o; o >>= 1) q += __shfl_xor_sync(0xffffffffu, q, o);
    float rstd = rsqrtf(q * (1.f / HD_) + EPS);
    out[(long)idx * HD_ + l]      = d0 * rstd * w[h * HD_ + l]      + b[h * HD_ + l];
    out[(long)idx * HD_ + l + 32] = d1 * rstd * w[h * HD_ + l + 32] + b[h * HD_ + l + 32];
}

// ---------------- softmax in place over V=8192 -------------------------------
__global__ void softmax_v_kernel(float* __restrict__ data) {
    long row = blockIdx.x;
    float* p = data + row * V_;
    int tid = threadIdx.x;  // 256
    float v[32];
    float mx = -INFINITY;
    #pragma unroll
    for (int i = 0; i < 32; i++) { v[i] = p[tid + i * 256]; mx = fmaxf(mx, v[i]); }
    mx = block_reduce_max(mx);
    float s = 0.f;
    #pragma unroll
    for (int i = 0; i < 32; i++) { v[i] = __expf(v[i] - mx); s += v[i]; }
    s = block_reduce_sum(s);
    float inv = 1.f / s;
    #pragma unroll
    for (int i = 0; i < 32; i++) p[tid + i * 256] = v[i] * inv;
}

// ---------------- xe_new + per-row loss partials ------------------------------
__global__ void xe_loss_kernel(const float* __restrict__ xe, const float* __restrict__ xhat,
                               const float* __restrict__ xrec, float* __restrict__ xe_new,
                               float* __restrict__ partial) {
    int idx = blockIdx.x;          // h*T + t
    int h = idx >> 10;
    int t = idx & 1023;
    int e = threadIdx.x;           // 64 threads
    long off = (long)idx * HD_ + e;
    float r = xrec[off];
    float dd = xhat[off] - r;
    xe_new[(long)t * D_ + h * HD_ + e] = xe[(long)t * D_ + h * HD_ + e] + r;
    float q = dd * dd;
    int lane = e & 31, wid = e >> 5;
    #pragma unroll
    for (int o = 16; o; o >>= 1) q += __shfl_xor_sync(0xffffffffu, q, o);
    __shared__ float sm[2];
    if (lane == 0) sm[wid] = q;
    __syncthreads();
    if (e == 0) partial[idx] = sm[0] + sm[1];
}

__global__ void loss_final_kernel(const float* __restrict__ partial, float* __restrict__ out) {
    float s = 0.f;
    for (int i = threadIdx.x; i < H_ * T_; i += 256) s += partial[i];
    s = block_reduce_sum(s);
    if (threadIdx.x == 0) out[0] = s / (float)(H_ * T_ * HD_);
}

// ---------------- launch ------------------------------------------------------
extern "C" void kernel_launch(void* const* d_in, const int* in_sizes, int n_in,
                              void* d_out, int out_size) {
    const float* xt       = (const float*)d_in[0];
    const float* xe       = (const float*)d_in[1];
    const float* ln1_w    = (const float*)d_in[2];
    const float* ln1_b    = (const float*)d_in[3];
    const float* qk_w     = (const float*)d_in[4];
    const float* qk_b     = (const float*)d_in[5];
    const float* v_fact   = (const float*)d_in[6];
    const float* out_fact = (const float*)d_in[7];
    const float* ln2_w    = (const float*)d_in[8];
    const float* ln2_b    = (const float*)d_in[9];
    const float* fc_w     = (const float*)d_in[10];
    const float* fc_b     = (const float*)d_in[11];
    const float* proj_w   = (const float*)d_in[12];
    const float* proj_b   = (const float*)d_in[13];
    const float* dln_w    = (const float*)d_in[14];
    const float* dln_b    = (const float*)d_in[15];
    const float* dict_emb = (const float*)d_in[16];

    float* out = (float*)d_out;
    float* out_xt   = out;                                   // [T,D]
    float* out_xe   = out + (long long)T_ * D_;              // [T,D]
    float* out_w    = out + 2LL * T_ * D_;                   // [H,T,V]
    float* out_loss = out + 2LL * T_ * D_ + (long long)H_ * T_ * V_; // scalar

    float *p_xnorm, *p_qk, *p_v, *p_y, *p_x2, *p_h, *p_h2, *p_xhat, *p_xrec, *p_lpart;
    cudaGetSymbolAddress((void**)&p_xnorm, g_xnorm);
    cudaGetSymbolAddress((void**)&p_qk,    g_qk);
    cudaGetSymbolAddress((void**)&p_v,     g_v);
    cudaGetSymbolAddress((void**)&p_y,     g_y);
    cudaGetSymbolAddress((void**)&p_x2,    g_x2);
    cudaGetSymbolAddress((void**)&p_h,     g_h);
    cudaGetSymbolAddress((void**)&p_h2,    g_h2);
    cudaGetSymbolAddress((void**)&p_xhat,  g_xhat);
    cudaGetSymbolAddress((void**)&p_xrec,  g_xrec);
    cudaGetSymbolAddress((void**)&p_lpart, g_lpart);

    dim3 blk(256);

    // 1. x_norm = LN1(xt + xe)
    add_ln_kernel<<<T_, 256>>>(xt, xe, ln1_w, ln1_b, p_xnorm);

    // 2. qk = x_norm @ qk_w^T + qk_b   [1024,1536]
    gemm_bias<true, false><<<dim3((2 * D_) / 64, T_ / 64, 1), blk>>>(
        p_xnorm, qk_w, qk_b, p_qk, T_, 2 * D_, D_, 0, 0, 0, 0, D_, D_, 2 * D_);

    // 3. v per head
    v_mix_kernel<<<dim3(T_, H_), HD_>>>(xt, v_fact, p_v);

    // 4. attention -> y [T,H,64]
    attn_kernel<<<dim3(T_, H_), 256>>>(p_qk, p_v, p_y);

    // 5. xt_new = xt + out_fact-mixed y
    mix_out_kernel<<<(T_ * D_ + 255) / 256, 256>>>(xt, out_fact, p_y, out_xt);

    // 6. x2 = LN2(xt_new + xe)
    add_ln_kernel<<<T_, 256>>>(out_xt, xe, ln2_w, ln2_b, p_x2);

    // 7. h = gelu(x2 @ fc_w_h^T + fc_b_h)   batched over heads -> [H,T,FF]
    gemm_bias<true, true><<<dim3(FF_ / 64, T_ / 64, H_), blk>>>(
        p_x2, fc_w, fc_b, p_h, T_, FF_, D_,
        0LL, (long long)FF_ * D_, FF_, (long long)T_ * FF_, D_, D_, FF_);

    // 8. h2 = h @ proj_w_h^T + proj_b_h -> [H,T,64]
    gemm_bias<true, false><<<dim3(1, T_ / 64, H_), blk>>>(
        p_h, proj_w, proj_b, p_h2, T_, HD_, FF_,
        (long long)T_ * FF_, (long long)HD_ * FF_, HD_, (long long)T_ * HD_, FF_, FF_, HD_);

    // 9. x_hat = LN64(h2) * dln_w + dln_b
    ln64_kernel<<<H_ * T_, 32>>>(p_h2, dln_w, dln_b, p_xhat);

    // 10. logits = x_hat @ dict_emb_h^T -> out_w [H,T,V]
    gemm_bias<true, false><<<dim3(V_ / 64, T_ / 64, H_), blk>>>(
        p_xhat, dict_emb, nullptr, out_w, T_, V_, HD_,
        (long long)T_ * HD_, (long long)V_ * HD_, 0, (long long)T_ * V_, HD_, HD_, V_);

    // 11. softmax rows of 8192 in place
    softmax_v_kernel<<<H_ * T_, 256>>>(out_w);

    // 12. x_recon = weights @ dict_emb_h -> [H,T,64]
    gemm_bias<false, false><<<dim3(1, T_ / 64, H_), blk>>>(
        out_w, dict_emb, nullptr, p_xrec, T_, HD_, V_,
        (long long)T_ * V_, (long long)V_ * HD_, 0, (long long)T_ * HD_, V_, HD_, HD_);

    // 13. xe_new + loss partials, then deterministic final reduce
    xe_loss_kernel<<<H_ * T_, 64>>>(xe, p_xhat, p_xrec, out_xe, p_lpart);
    loss_final_kernel<<<1, 256>>>(p_lpart, out_loss);
}

// round 7
// speedup vs baseline: 1.0013x; 1.0013x over previous
#include <cuda_runtime.h>
#include <math.h>

// Problem constants
#define T_  1024
#define D_  768
#define H_  12
#define HD_ 64
#define FF_ 3072
#define V_  8192
#define EPS 1e-5f

// ---------------- scratch (device globals; allocation-free) ----------------
__device__ float g_xnorm [T_ * D_];                 // ln1 output
__device__ float g_qk    [T_ * 2 * D_];             // qk projection [T, 1536]
__device__ float g_v     [H_ * T_ * HD_];           // v per head [H,T,64]
__device__ float g_y     [T_ * H_ * HD_];           // attn out [T,H,64]
__device__ float g_x2    [T_ * D_];                 // ln2 output
__device__ float g_h     [(long long)H_ * T_ * FF_];// gelu(fc) [H,T,FF]  (~151MB)
__device__ float g_h2    [H_ * T_ * HD_];           // proj out [H,T,64]
__device__ float g_xhat  [H_ * T_ * HD_];           // dict LN out
__device__ float g_xrec  [H_ * T_ * HD_];           // reconstruction
__device__ float g_lpart [H_ * T_];                 // per-(h,t) loss partials

// ALiBi slopes for H=12 (closest power 8 + extras), computed in double, hardcoded
__constant__ float c_slopes[H_] = {
    0.5f, 0.25f, 0.125f, 0.0625f, 0.03125f, 0.015625f, 0.0078125f, 0.00390625f,
    0.70710678118654752f, 0.5f, 0.35355339059327376f, 0.25f
};

// ---------------- reduction helpers ----------------
__device__ __forceinline__ float block_reduce_sum(float v) {
    __shared__ float sm[33];
    int lane = threadIdx.x & 31, wid = threadIdx.x >> 5;
    #pragma unroll
    for (int o = 16; o; o >>= 1) v += __shfl_xor_sync(0xffffffffu, v, o);
    __syncthreads();
    if (lane == 0) sm[wid] = v;
    __syncthreads();
    int nw = (blockDim.x + 31) >> 5;
    if (wid == 0) {
        v = (lane < nw) ? sm[lane] : 0.f;
        #pragma unroll
        for (int o = 16; o; o >>= 1) v += __shfl_xor_sync(0xffffffffu, v, o);
        if (lane == 0) sm[32] = v;
    }
    __syncthreads();
    return sm[32];
}

__device__ __forceinline__ float block_reduce_max(float v) {
    __shared__ float sm[33];
    int lane = threadIdx.x & 31, wid = threadIdx.x >> 5;
    #pragma unroll
    for (int o = 16; o; o >>= 1) v = fmaxf(v, __shfl_xor_sync(0xffffffffu, v, o));
    __syncthreads();
    if (lane == 0) sm[wid] = v;
    __syncthreads();
    int nw = (blockDim.x + 31) >> 5;
    if (wid == 0) {
        v = (lane < nw) ? sm[lane] : -INFINITY;
        #pragma unroll
        for (int o = 16; o; o >>= 1) v = fmaxf(v, __shfl_xor_sync(0xffffffffu, v, o));
        if (lane == 0) sm[32] = v;
    }
    __syncthreads();
    return sm[32];
}

// ---------------- add + layernorm over D=768 ----------------
__global__ void add_ln_kernel(const float* __restrict__ a, const float* __restrict__ b,
                              const float* __restrict__ w, const float* __restrict__ bs,
                              float* __restrict__ out) {
    int t = blockIdx.x;
    long base = (long)t * D_;
    float x[3];
    float s = 0.f;
    #pragma unroll
    for (int i = 0; i < 3; i++) {
        int c = threadIdx.x + 256 * i;
        x[i] = a[base + c] + b[base + c];
        s += x[i];
    }
    s = block_reduce_sum(s);
    float mu = s * (1.f / D_);
    float q = 0.f;
    #pragma unroll
    for (int i = 0; i < 3; i++) { float d = x[i] - mu; q += d * d; }
    q = block_reduce_sum(q);
    float rstd = rsqrtf(q * (1.f / D_) + EPS);
    #pragma unroll
    for (int i = 0; i < 3; i++) {
        int c = threadIdx.x + 256 * i;
        out[base + c] = (x[i] - mu) * rstd * w[c] + bs[c];
    }
}

// ---------------- generic batched tiled GEMM: C = A * op(B) + bias ----------
// A: [M,K] row-major (lda). TRANS_B: B is [N,K] (ldb over K); else B is [K,N].
// 64x64x16 tiles, 256 threads, 4x4 per thread. All dims assumed divisible.
template<bool TRANS_B, bool GELU>
__global__ void gemm_bias(const float* __restrict__ A, const float* __restrict__ B,
                          const float* __restrict__ bias, float* __restrict__ C,
                          int M, int N, int K,
                          long long sA, long long sB, long long sBias, long long sC,
                          int lda, int ldb, int ldc) {
    int bz = blockIdx.z;
    A += bz * sA; B += bz * sB; C += bz * sC;
    if (bias) bias += bz * sBias;

    __shared__ float As[16][64];
    __shared__ float Bs[16][64];

    int tid = threadIdx.x;
    int row0 = blockIdx.y * 64;
    int col0 = blockIdx.x * 64;
    int tr = (tid >> 4) * 4;
    int tc = (tid & 15) * 4;

    float acc[4][4] = {};

    for (int k0 = 0; k0 < K; k0 += 16) {
        { // A tile (transposed store)
            int r  = tid >> 2;
            int kk = (tid & 3) * 4;
            float4 v = *(const float4*)(A + (long)(row0 + r) * lda + k0 + kk);
            As[kk + 0][r] = v.x; As[kk + 1][r] = v.y;
            As[kk + 2][r] = v.z; As[kk + 3][r] = v.w;
        }
        if (TRANS_B) {
            int n  = tid >> 2;
            int kk = (tid & 3) * 4;
            float4 v = *(const float4*)(B + (long)(col0 + n) * ldb + k0 + kk);
            Bs[kk + 0][n] = v.x; Bs[kk + 1][n] = v.y;
            Bs[kk + 2][n] = v.z; Bs[kk + 3][n] = v.w;
        } else {
            int kk = tid >> 4;
            int n  = (tid & 15) * 4;
            float4 v = *(const float4*)(B + (long)(k0 + kk) * ldb + col0 + n);
            Bs[kk][n] = v.x; Bs[kk][n + 1] = v.y; Bs[kk][n + 2] = v.z; Bs[kk][n + 3] = v.w;
        }
        __syncthreads();
        #pragma unroll
        for (int kk = 0; kk < 16; kk++) {
            float a[4], b[4];
            #pragma unroll
            for (int i = 0; i < 4; i++) a[i] = As[kk][tr + i];
            #pragma unroll
            for (int j = 0; j < 4; j++) b[j] = Bs[kk][tc + j];
            #pragma unroll
            for (int i = 0; i < 4; i++)
                #pragma unroll
                for (int j = 0; j < 4; j++)
                    acc[i][j] += a[i] * b[j];
        }
        __syncthreads();
    }
    #pragma unroll
    for (int i = 0; i < 4; i++) {
        long r = row0 + tr + i;
        #pragma unroll
        for (int j = 0; j < 4; j++) {
            int c = col0 + tc + j;
            float v = acc[i][j];
            if (bias) v += bias[c];
            if (GELU) v = 0.5f * v * (1.0f + erff(v * 0.70710678118654752f));
            C[r * ldc + c] = v;
        }
    }
}

// ---------------- v = per-head mix of xt heads by v_fact --------------------
__global__ void v_mix_kernel(const float* __restrict__ xt, const float* __restrict__ vf,
                             float* __restrict__ v) {
    int t = blockIdx.x, h = blockIdx.y, d = threadIdx.x;
    float acc = 0.f;
    #pragma unroll
    for (int j = 0; j < H_; j++)
        acc += vf[h * H_ + j] * xt[(long)t * D_ + j * HD_ + d];
    v[((long)h * T_ + t) * HD_ + d] = acc;
}

// ---------------- attention: one block per (query i, head h) ----------------
__global__ void attn_kernel(const float* __restrict__ qk, const float* __restrict__ v,
                            float* __restrict__ y) {
    int i = blockIdx.x, h = blockIdx.y;
    __shared__ float qs[HD_];
    __shared__ float ss[T_];
    __shared__ float red[256];
    int tid = threadIdx.x;

    if (tid < HD_) qs[tid] = qk[(long)i * (2 * D_) + h * HD_ + tid];
    __syncthreads();

    float slope = c_slopes[h];
    float lmax = -INFINITY;
    for (int j = tid; j < T_; j += 256) {
        float s;
        if (j <= i) {
            const float* kp = qk + (long)j * (2 * D_) + D_ + h * HD_;
            float d = 0.f;
            #pragma unroll
            for (int e = 0; e < HD_; e++) d += qs[e] * kp[e];
            s = d * 0.125f + slope * (float)(j - i);
        } else s = -INFINITY;
        ss[j] = s;
        lmax = fmaxf(lmax, s);
    }
    float mx = block_reduce_max(lmax);

    float lsum = 0.f;
    for (int j = tid; j < T_; j += 256) {
        float e = (j <= i) ? __expf(ss[j] - mx) : 0.f;
        ss[j] = e;
        lsum += e;
    }
    float total = block_reduce_sum(lsum);

    // output: 4 chunks x 64 dims
    int d = tid & 63, c = tid >> 6;
    float acc = 0.f;
    for (int j = c; j <= i; j += 4)
        acc += ss[j] * v[((long)h * T_ + j) * HD_ + d];
    red[tid] = acc;
    __syncthreads();
    if (tid < HD_) {
        float o = (red[tid] + red[tid + 64] + red[tid + 128] + red[tid + 192]) / total;
        y[((long)i * H_ + h) * HD_ + tid] = o;
    }
}

// ---------------- output mix + residual: xt_new -----------------------------
__global__ void mix_out_kernel(const float* __restrict__ xt, const float* __restrict__ of,
                               const float* __restrict__ y, float* __restrict__ xt_new) {
    int idx = blockIdx.x * 256 + threadIdx.x;
    if (idx >= T_ * D_) return;
    int t = idx / D_;
    int c = idx - t * D_;
    int i = c >> 6, d = c & 63;
    float acc = xt[idx];
    #pragma unroll
    for (int j = 0; j < H_; j++)
        acc += of[i * H_ + j] * y[((long)t * H_ + j) * HD_ + d];
    xt_new[idx] = acc;
}

// ---------------- layernorm over HD=64 (dict LN) -----------------------------
__global__ void ln64_kernel(const float* __restrict__ in, const float* __restrict__ w,
                            const float* __restrict__ b, float* __restrict__ out) {
    int idx = blockIdx.x;          // h*T + t
    int h = idx >> 10;
    int l = threadIdx.x;           // 32 threads
    const float* p = in + (long)idx * HD_;
    float x0 = p[l], x1 = p[l + 32];
    float s = x0 + x1;
    #pragma unroll
    for (int o = 16; o; o >>= 1) s += __shfl_xor_sync(0xffffffffu, s, o);
    float mu = s * (1.f / HD_);
    float d0 = x0 - mu, d1 = x1 - mu;
    float q = d0 * d0 + d1 * d1;
    #pragma unroll
    for (int o = 16; o; o >>= 1) q += __shfl_xor_sync(0xffffffffu, q, o);
    float rstd = rsqrtf(q * (1.f / HD_) + EPS);
    out[(long)idx * HD_ + l]      = d0 * rstd * w[h * HD_ + l]      + b[h * HD_ + l];
    out[(long)idx * HD_ + l + 32] = d1 * rstd * w[h * HD_ + l + 32] + b[h * HD_ + l + 32];
}

// ---------------- softmax in place over V=8192 -------------------------------
__global__ void softmax_v_kernel(float* __restrict__ data) {
    long row = blockIdx.x;
    float* p = data + row * V_;
    int tid = threadIdx.x;  // 256
    float v[32];
    float mx = -INFINITY;
    #pragma unroll
    for (int i = 0; i < 32; i++) { v[i] = p[tid + i * 256]; mx = fmaxf(mx, v[i]); }
    mx = block_reduce_max(mx);
    float s = 0.f;
    #pragma unroll
    for (int i = 0; i < 32; i++) { v[i] = __expf(v[i] - mx); s += v[i]; }
    s = block_reduce_sum(s);
    float inv = 1.f / s;
    #pragma unroll
    for (int i = 0; i < 32; i++) p[tid + i * 256] = v[i] * inv;
}

// ---------------- xe_new + per-row loss partials ------------------------------
__global__ void xe_loss_kernel(const float* __restrict__ xe, const float* __restrict__ xhat,
                               const float* __restrict__ xrec, float* __restrict__ xe_new,
                               float* __restrict__ partial) {
    int idx = blockIdx.x;          // h*T + t
    int h = idx >> 10;
    int t = idx & 1023;
    int e = threadIdx.x;           // 64 threads
    long off = (long)idx * HD_ + e;
    float r = xrec[off];
    float dd = xhat[off] - r;
    xe_new[(long)t * D_ + h * HD_ + e] = xe[(long)t * D_ + h * HD_ + e] + r;
    float q = dd * dd;
    int lane = e & 31, wid = e >> 5;
    #pragma unroll
    for (int o = 16; o; o >>= 1) q += __shfl_xor_sync(0xffffffffu, q, o);
    __shared__ float sm[2];
    if (lane == 0) sm[wid] = q;
    __syncthreads();
    if (e == 0) partial[idx] = sm[0] + sm[1];
}

__global__ void loss_final_kernel(const float* __restrict__ partial, float* __restrict__ out) {
    float s = 0.f;
    for (int i = threadIdx.x; i < H_ * T_; i += 256) s += partial[i];
    s = block_reduce_sum(s);
    if (threadIdx.x == 0) out[0] = s / (float)(H_ * T_ * HD_);
}

// ---------------- launch ------------------------------------------------------
extern "C" void kernel_launch(void* const* d_in, const int* in_sizes, int n_in,
                              void* d_out, int out_size) {
    const float* xt       = (const float*)d_in[0];
    const float* xe       = (const float*)d_in[1];
    const float* ln1_w    = (const float*)d_in[2];
    const float* ln1_b    = (const float*)d_in[3];
    const float* qk_w     = (const float*)d_in[4];
    const float* qk_b     = (const float*)d_in[5];
    const float* v_fact   = (const float*)d_in[6];
    const float* out_fact = (const float*)d_in[7];
    const float* ln2_w    = (const float*)d_in[8];
    const float* ln2_b    = (const float*)d_in[9];
    const float* fc_w     = (const float*)d_in[10];
    const float* fc_b     = (const float*)d_in[11];
    const float* proj_w   = (const float*)d_in[12];
    const float* proj_b   = (const float*)d_in[13];
    const float* dln_w    = (const float*)d_in[14];
    const float* dln_b    = (const float*)d_in[15];
    const float* dict_emb = (const float*)d_in[16];

    float* out = (float*)d_out;
    float* out_xt   = out;                                   // [T,D]
    float* out_xe   = out + (long long)T_ * D_;              // [T,D]
    float* out_w    = out + 2LL * T_ * D_;                   // [H,T,V]
    float* out_loss = out + 2LL * T_ * D_ + (long long)H_ * T_ * V_; // scalar

    float *p_xnorm, *p_qk, *p_v, *p_y, *p_x2, *p_h, *p_h2, *p_xhat, *p_xrec, *p_lpart;
    cudaGetSymbolAddress((void**)&p_xnorm, g_xnorm);
    cudaGetSymbolAddress((void**)&p_qk,    g_qk);
    cudaGetSymbolAddress((void**)&p_v,     g_v);
    cudaGetSymbolAddress((void**)&p_y,     g_y);
    cudaGetSymbolAddress((void**)&p_x2,    g_x2);
    cudaGetSymbolAddress((void**)&p_h,     g_h);
    cudaGetSymbolAddress((void**)&p_h2,    g_h2);
    cudaGetSymbolAddress((void**)&p_xhat,  g_xhat);
    cudaGetSymbolAddress((void**)&p_xrec,  g_xrec);
    cudaGetSymbolAddress((void**)&p_lpart, g_lpart);

    dim3 blk(256);

    // 1. x_norm = LN1(xt + xe)
    add_ln_kernel<<<T_, 256>>>(xt, xe, ln1_w, ln1_b, p_xnorm);

    // 2. qk = x_norm @ qk_w^T + qk_b   [1024,1536]
    gemm_bias<true, false><<<dim3((2 * D_) / 64, T_ / 64, 1), blk>>>(
        p_xnorm, qk_w, qk_b, p_qk, T_, 2 * D_, D_, 0, 0, 0, 0, D_, D_, 2 * D_);

    // 3. v per head
    v_mix_kernel<<<dim3(T_, H_), HD_>>>(xt, v_fact, p_v);

    // 4. attention -> y [T,H,64]
    attn_kernel<<<dim3(T_, H_), 256>>>(p_qk, p_v, p_y);

    // 5. xt_new = xt + out_fact-mixed y
    mix_out_kernel<<<(T_ * D_ + 255) / 256, 256>>>(xt, out_fact, p_y, out_xt);

    // 6. x2 = LN2(xt_new + xe)
    add_ln_kernel<<<T_, 256>>>(out_xt, xe, ln2_w, ln2_b, p_x2);

    // 7. h = gelu(x2 @ fc_w_h^T + fc_b_h)   batched over heads -> [H,T,FF]
    gemm_bias<true, true><<<dim3(FF_ / 64, T_ / 64, H_), blk>>>(
        p_x2, fc_w, fc_b, p_h, T_, FF_, D_,
        0LL, (long long)FF_ * D_, FF_, (long long)T_ * FF_, D_, D_, FF_);

    // 8. h2 = h @ proj_w_h^T + proj_b_h -> [H,T,64]
    gemm_bias<true, false><<<dim3(1, T_ / 64, H_), blk>>>(
        p_h, proj_w, proj_b, p_h2, T_, HD_, FF_,
        (long long)T_ * FF_, (long long)HD_ * FF_, HD_, (long long)T_ * HD_, FF_, FF_, HD_);

    // 9. x_hat = LN64(h2) * dln_w + dln_b
    ln64_kernel<<<H_ * T_, 32>>>(p_h2, dln_w, dln_b, p_xhat);

    // 10. logits = x_hat @ dict_emb_h^T -> out_w [H,T,V]
    gemm_bias<true, false><<<dim3(V_ / 64, T_ / 64, H_), blk>>>(
        p_xhat, dict_emb, nullptr, out_w, T_, V_, HD_,
        (long long)T_ * HD_, (long long)V_ * HD_, 0, (long long)T_ * V_, HD_, HD_, V_);

    // 11. softmax rows of 8192 in place
    softmax_v_kernel<<<H_ * T_, 256>>>(out_w);

    // 12. x_recon = weights @ dict_emb_h -> [H,T,64]
    gemm_bias<false, false><<<dim3(1, T_ / 64, H_), blk>>>(
        out_w, dict_emb, nullptr, p_xrec, T_, HD_, V_,
        (long long)T_ * V_, (long long)V_ * HD_, 0, (long long)T_ * HD_, V_, HD_, HD_);

    // 13. xe_new + loss partials, then deterministic final reduce
    xe_loss_kernel<<<H_ * T_, 64>>>(xe, p_xhat, p_xrec, out_xe, p_lpart);
    loss_final_kernel<<<1, 256>>>(p_lpart, out_loss);
}